// round 6
// baseline (speedup 1.0000x reference)
#include <cuda_runtime.h>

#define Hh 51
#define H4 204
#define TT 1024
#define NCTA 128
#define NTHR 448

// ---- shared memory (float offsets) ----
// sW1  [204][52] W_hh1 (col 51 = 0), stride 52 -> conflict-free
// sW2i [204][52] W_ih2, sW2h [204][52] W_hh2
// sWlin[52]; sX [1024][8] t-major; sH1 [2][52][8]; sH2 [2][52][8]
#define OFF_W1   0
#define OFF_W2I  10608
#define OFF_W2H  21216
#define OFF_WLIN 31824
#define OFF_X    31880
#define OFF_H1   40072
#define OFF_H2   40904
#define SMEM_FLOATS 41736
#define SMEM_BYTES (SMEM_FLOATS * 4)

typedef unsigned long long u64;

__device__ __forceinline__ u64 splat2(float w) {
    unsigned int wi = __float_as_uint(w);
    u64 r;
    asm("mov.b64 %0, {%1, %1};" : "=l"(r) : "r"(wi));
    return r;
}
__device__ __forceinline__ void ffma2(u64& d, u64 a, u64 b) {
    asm("fma.rn.f32x2 %0, %1, %2, %0;" : "+l"(d) : "l"(a), "l"(b));
}
__device__ __forceinline__ float2 u2f(u64 v) {
    float2 f;
    asm("mov.b64 {%0, %1}, %2;" : "=f"(f.x), "=f"(f.y) : "l"(v));
    return f;
}
__device__ __forceinline__ u64 f2u(float x, float y) {
    u64 v;
    asm("mov.b64 %0, {%1, %2};" : "=l"(v) : "f"(x), "f"(y));
    return v;
}
__device__ __forceinline__ float sigf(float x) {
    return __fdividef(1.0f, 1.0f + __expf(-x));
}
__device__ __forceinline__ float tanhfast(float x) {
    return 1.0f - __fdividef(2.0f, __expf(2.0f * x) + 1.0f);
}

// accumulate 13 quads (52 k) of 4 gate rows into ai/af/ag/ao
#define QUADS13(wp0, wp1, wp2, wp3, hrd) { \
    _Pragma("unroll") \
    for (int kk = 0; kk < 13; ++kk) { \
        const float4 wi = *(const float4*)((wp0) + kk * 4); \
        const float4 wf = *(const float4*)((wp1) + kk * 4); \
        const float4 wg = *(const float4*)((wp2) + kk * 4); \
        const float4 wo = *(const float4*)((wp3) + kk * 4); \
        const u64 h0 = *(const u64*)((hrd) + (kk * 4 + 0) * 8); \
        const u64 h1v = *(const u64*)((hrd) + (kk * 4 + 1) * 8); \
        const u64 h2v = *(const u64*)((hrd) + (kk * 4 + 2) * 8); \
        const u64 h3v = *(const u64*)((hrd) + (kk * 4 + 3) * 8); \
        ffma2(ai, splat2(wi.x), h0);  ffma2(ai, splat2(wi.y), h1v); \
        ffma2(ai, splat2(wi.z), h2v); ffma2(ai, splat2(wi.w), h3v); \
        ffma2(af, splat2(wf.x), h0);  ffma2(af, splat2(wf.y), h1v); \
        ffma2(af, splat2(wf.z), h2v); ffma2(af, splat2(wf.w), h3v); \
        ffma2(ag, splat2(wg.x), h0);  ffma2(ag, splat2(wg.y), h1v); \
        ffma2(ag, splat2(wg.z), h2v); ffma2(ag, splat2(wg.w), h3v); \
        ffma2(ao, splat2(wo.x), h0);  ffma2(ao, splat2(wo.y), h1v); \
        ffma2(ao, splat2(wo.z), h2v); ffma2(ao, splat2(wo.w), h3v); \
    } }

// in-register LSTM update: accs -> (c, h_packed)
#define UPDATE(cvar, hout) { \
    const float2 gi = u2f(ai), gf = u2f(af), gg = u2f(ag), go = u2f(ao); \
    const float i0 = sigf(gi.x), f0 = sigf(gf.x), g0 = tanhfast(gg.x), o0 = sigf(go.x); \
    const float i1 = sigf(gi.y), f1 = sigf(gf.y), g1 = tanhfast(gg.y), o1 = sigf(go.y); \
    cvar.x = f0 * cvar.x + i0 * g0; \
    cvar.y = f1 * cvar.y + i1 * g1; \
    hout = f2u(o0 * tanhfast(cvar.x), o1 * tanhfast(cvar.y)); }

__global__ __launch_bounds__(NTHR, 1)
void lstm_seq_kernel(const float* __restrict__ input,
                     const float* __restrict__ W_ih1, const float* __restrict__ W_hh1,
                     const float* __restrict__ b_ih1, const float* __restrict__ b_hh1,
                     const float* __restrict__ W_ih2, const float* __restrict__ W_hh2,
                     const float* __restrict__ b_ih2, const float* __restrict__ b_hh2,
                     const float* __restrict__ W_lin, const float* __restrict__ b_lin,
                     float* __restrict__ out)
{
    extern __shared__ float sm[];
    float* sW1   = sm + OFF_W1;
    float* sW2i  = sm + OFF_W2I;
    float* sW2h  = sm + OFF_W2H;
    float* sWlin = sm + OFF_WLIN;
    float* sX    = sm + OFF_X;
    float* sH1   = sm + OFF_H1;   // [2][52*8]
    float* sH2   = sm + OFF_H2;   // [2][52*8]

    const int tid = threadIdx.x;
    const int b0  = blockIdx.x * 8;

    // ---------------- staging ----------------
    for (int i = tid; i < H4 * Hh; i += NTHR) {
        const int r = i / Hh, k = i % Hh;
        sW1[r * 52 + k]  = W_hh1[i];
        sW2i[r * 52 + k] = W_ih2[i];
        sW2h[r * 52 + k] = W_hh2[i];
    }
    for (int r = tid; r < H4; r += NTHR) {
        sW1[r * 52 + 51]  = 0.0f;
        sW2i[r * 52 + 51] = 0.0f;
        sW2h[r * 52 + 51] = 0.0f;
    }
    if (tid < Hh) sWlin[tid] = W_lin[tid];
    for (int i = tid; i < 8 * TT; i += NTHR) {
        const int b = i >> 10, t = i & 1023;
        sX[t * 8 + b] = input[b0 * TT + i];
    }
    for (int i = tid; i < 832; i += NTHR) { sH1[i] = 0.0f; sH2[i] = 0.0f; }

    // ---------------- roles ----------------
    const bool isA = (tid < 224);
    const int  lt  = isA ? tid : (tid - 224);
    const int  j   = lt >> 2;
    const int  bo2 = (lt & 3) * 2;
    const bool act = (j < Hh);
    const int  ri = j, rf = Hh + j, rg = 2 * Hh + j, ro = 3 * Hh + j;

    // group A: layer-1 constants
    u64 bA_i = 0, bA_f = 0, bA_g = 0, bA_o = 0;
    u64 wxi = 0, wxf = 0, wxg = 0, wxo = 0;
    const float* wA0 = sW1;  const float* wA1 = sW1;
    const float* wA2 = sW1;  const float* wA3 = sW1;
    // group B: layer-2 constants
    u64 bB_i = 0, bB_f = 0, bB_g = 0, bB_o = 0;
    const float* wI0 = sW2i; const float* wI1 = sW2i;
    const float* wI2 = sW2i; const float* wI3 = sW2i;
    const float* wH0 = sW2h; const float* wH1 = sW2h;
    const float* wH2 = sW2h; const float* wH3 = sW2h;

    if (act) {
        if (isA) {
            bA_i = splat2(b_ih1[ri] + b_hh1[ri]);
            bA_f = splat2(b_ih1[rf] + b_hh1[rf]);
            bA_g = splat2(b_ih1[rg] + b_hh1[rg]);
            bA_o = splat2(b_ih1[ro] + b_hh1[ro]);
            wxi = splat2(W_ih1[ri]); wxf = splat2(W_ih1[rf]);
            wxg = splat2(W_ih1[rg]); wxo = splat2(W_ih1[ro]);
            wA0 = sW1 + ri * 52; wA1 = sW1 + rf * 52;
            wA2 = sW1 + rg * 52; wA3 = sW1 + ro * 52;
        } else {
            bB_i = splat2(b_ih2[ri] + b_hh2[ri]);
            bB_f = splat2(b_ih2[rf] + b_hh2[rf]);
            bB_g = splat2(b_ih2[rg] + b_hh2[rg]);
            bB_o = splat2(b_ih2[ro] + b_hh2[ro]);
            wI0 = sW2i + ri * 52; wI1 = sW2i + rf * 52;
            wI2 = sW2i + rg * 52; wI3 = sW2i + ro * 52;
            wH0 = sW2h + ri * 52; wH1 = sW2h + rf * 52;
            wH2 = sW2h + rg * 52; wH3 = sW2h + ro * 52;
        }
    }

    float2 c1 = make_float2(0.0f, 0.0f);
    float2 c2 = make_float2(0.0f, 0.0f);
    u64 p_i = bB_i, p_f = bB_f, p_g = bB_g, p_o = bB_o;  // B: hh2 partial (step 0: h2=0 -> bias only)
    const float blin = b_lin[0];

    __syncthreads();

    // ---------------- prologue: A computes L1 step 0 (h1_prev = 0) ----------------
    if (isA && act) {
        u64 ai = bA_i, af = bA_f, ag = bA_g, ao = bA_o;
        const u64 xv = *(const u64*)(sX + 0 * 8 + bo2);
        ffma2(ai, wxi, xv); ffma2(af, wxf, xv);
        ffma2(ag, wxg, xv); ffma2(ao, wxo, xv);
        const float* hrd = sH1 + 416 + bo2;      // buffer 1 (zeros)
        QUADS13(wA0, wA1, wA2, wA3, hrd);
        u64 hnew;
        UPDATE(c1, hnew);
        *(u64*)(sH1 + 0 * 416 + j * 8 + bo2) = hnew;   // h1(0) -> buf 0
    }
    __syncthreads();

    // ---------------- time loop: 2 phases ----------------
    for (int t = 0; t < TT; ++t) {
        const int pt = t & 1, pn = (t + 1) & 1;

        // ===== Phase P =====
        if (isA) {
            if (act && t < TT - 1) {
                // layer-1 cell for step t+1: reads h1(t) [buf pt], x(t+1); writes h1(t+1) [buf pn]
                u64 ai = bA_i, af = bA_f, ag = bA_g, ao = bA_o;
                const u64 xv = *(const u64*)(sX + (t + 1) * 8 + bo2);
                ffma2(ai, wxi, xv); ffma2(af, wxf, xv);
                ffma2(ag, wxg, xv); ffma2(ao, wxo, xv);
                const float* hrd = sH1 + pt * 416 + bo2;
                QUADS13(wA0, wA1, wA2, wA3, hrd);
                u64 hnew;
                UPDATE(c1, hnew);
                *(u64*)(sH1 + pn * 416 + j * 8 + bo2) = hnew;
            }
        } else if (act) {
            // layer-2 cell for step t: ih2 part (reads h1(t) [buf pt]) + held hh2 partial; writes h2(t) [buf pt]
            u64 ai = p_i, af = p_f, ag = p_g, ao = p_o;
            const float* hrd = sH1 + pt * 416 + bo2;
            QUADS13(wI0, wI1, wI2, wI3, hrd);
            u64 hnew;
            UPDATE(c2, hnew);
            *(u64*)(sH2 + pt * 416 + j * 8 + bo2) = hnew;
        }
        __syncthreads();

        // ===== Phase Q =====
        if (!isA) {
            if (act && t < TT - 1) {
                // hh2 partial for step t+1: reads h2(t) [buf pt]
                u64 ai = bB_i, af = bB_f, ag = bB_g, ao = bB_o;
                const float* hrd = sH2 + pt * 416 + bo2;
                QUADS13(wH0, wH1, wH2, wH3, hrd);
                p_i = ai; p_f = af; p_g = ag; p_o = ao;
            }
        } else if (tid < 8) {
            // head(t): y = W_lin . h2(t) + b
            const float* h2rd = sH2 + pt * 416;
            float s = blin;
            #pragma unroll
            for (int k = 0; k < Hh; ++k)
                s = fmaf(sWlin[k], h2rd[k * 8 + tid], s);
            out[(b0 + tid) * TT + t] = s;
        }
        __syncthreads();
    }
}

extern "C" void kernel_launch(void* const* d_in, const int* in_sizes, int n_in,
                              void* d_out, int out_size) {
    const float* input = (const float*)d_in[0];
    const float* W_ih1 = (const float*)d_in[1];
    const float* W_hh1 = (const float*)d_in[2];
    const float* b_ih1 = (const float*)d_in[3];
    const float* b_hh1 = (const float*)d_in[4];
    const float* W_ih2 = (const float*)d_in[5];
    const float* W_hh2 = (const float*)d_in[6];
    const float* b_ih2 = (const float*)d_in[7];
    const float* b_hh2 = (const float*)d_in[8];
    const float* W_lin = (const float*)d_in[9];
    const float* b_lin = (const float*)d_in[10];
    float* out = (float*)d_out;

    cudaFuncSetAttribute(lstm_seq_kernel,
                         cudaFuncAttributeMaxDynamicSharedMemorySize, SMEM_BYTES);
    lstm_seq_kernel<<<NCTA, NTHR, SMEM_BYTES>>>(
        input, W_ih1, W_hh1, b_ih1, b_hh1,
        W_ih2, W_hh2, b_ih2, b_hh2, W_lin, b_lin, out);
}

// round 7
// speedup vs baseline: 1.0867x; 1.0867x over previous
#include <cuda_runtime.h>

#define Hh 51
#define H4 204
#define TT 1024
#define NCTA 128
#define NTHR 672     // warps 0-6: L1 cells; 7-19: L2 half-cells; 20: head

// ---- shared memory (float offsets) ----
// sW1 [204][52] W_hh1; sW2i [204][52] W_ih2; sW2h [204][52] W_hh2 (col 51 = 0)
// sWlin[52]; sX [1024][8] t-major; sH1 [2][52][10]; sH2 [2][52][10]
#define OFF_W1   0
#define OFF_W2I  10608
#define OFF_W2H  21216
#define OFF_WLIN 31824
#define OFF_X    31880
#define OFF_H1   40072   // mod 32 = 8
#define OFF_H2   41112   // mod 32 = 24 -> diff 16: B's h1/h2 dual loads conflict-free
#define SMEM_FLOATS 42152
#define SMEM_BYTES  (SMEM_FLOATS * 4)

typedef unsigned long long u64;

__device__ __forceinline__ u64 splat2(float w) {
    unsigned int wi = __float_as_uint(w);
    u64 r;
    asm("mov.b64 %0, {%1, %1};" : "=l"(r) : "r"(wi));
    return r;
}
__device__ __forceinline__ void ffma2(u64& d, u64 a, u64 b) {
    asm("fma.rn.f32x2 %0, %1, %2, %0;" : "+l"(d) : "l"(a), "l"(b));
}
__device__ __forceinline__ u64 add2(u64 a, u64 b) {
    u64 r;
    asm("add.rn.f32x2 %0, %1, %2;" : "=l"(r) : "l"(a), "l"(b));
    return r;
}
__device__ __forceinline__ float2 u2f(u64 v) {
    float2 f;
    asm("mov.b64 {%0, %1}, %2;" : "=f"(f.x), "=f"(f.y) : "l"(v));
    return f;
}
__device__ __forceinline__ u64 f2u(float x, float y) {
    u64 v;
    asm("mov.b64 %0, {%1, %2};" : "=l"(v) : "f"(x), "f"(y));
    return v;
}
__device__ __forceinline__ float sigf(float x) {
    return __fdividef(1.0f, 1.0f + __expf(-x));
}
__device__ __forceinline__ float tanhfast(float x) {
    return 1.0f - __fdividef(2.0f, __expf(2.0f * x) + 1.0f);
}

// 13 quads (52 k) of 4 gate rows; h rows at stride 10
#define QUADS13(wp0, wp1, wp2, wp3, hrd) { \
    _Pragma("unroll") \
    for (int kk = 0; kk < 13; ++kk) { \
        const float4 wi = *(const float4*)((wp0) + kk * 4); \
        const float4 wf = *(const float4*)((wp1) + kk * 4); \
        const float4 wg = *(const float4*)((wp2) + kk * 4); \
        const float4 wo = *(const float4*)((wp3) + kk * 4); \
        const u64 h0  = *(const u64*)((hrd) + (kk * 4 + 0) * 10); \
        const u64 h1v = *(const u64*)((hrd) + (kk * 4 + 1) * 10); \
        const u64 h2v = *(const u64*)((hrd) + (kk * 4 + 2) * 10); \
        const u64 h3v = *(const u64*)((hrd) + (kk * 4 + 3) * 10); \
        ffma2(ai, splat2(wi.x), h0);  ffma2(ai, splat2(wi.y), h1v); \
        ffma2(ai, splat2(wi.z), h2v); ffma2(ai, splat2(wi.w), h3v); \
        ffma2(af, splat2(wf.x), h0);  ffma2(af, splat2(wf.y), h1v); \
        ffma2(af, splat2(wf.z), h2v); ffma2(af, splat2(wf.w), h3v); \
        ffma2(ag, splat2(wg.x), h0);  ffma2(ag, splat2(wg.y), h1v); \
        ffma2(ag, splat2(wg.z), h2v); ffma2(ag, splat2(wg.w), h3v); \
        ffma2(ao, splat2(wo.x), h0);  ffma2(ao, splat2(wo.y), h1v); \
        ffma2(ao, splat2(wo.z), h2v); ffma2(ao, splat2(wo.w), h3v); \
    } }

#define UPDATE(cvar, hout) { \
    const float2 gi = u2f(ai), gf = u2f(af), gg = u2f(ag), go = u2f(ao); \
    const float i0 = sigf(gi.x), f0 = sigf(gf.x), g0 = tanhfast(gg.x), o0 = sigf(go.x); \
    const float i1 = sigf(gi.y), f1 = sigf(gf.y), g1 = tanhfast(gg.y), o1 = sigf(go.y); \
    cvar.x = f0 * cvar.x + i0 * g0; \
    cvar.y = f1 * cvar.y + i1 * g1; \
    hout = f2u(o0 * tanhfast(cvar.x), o1 * tanhfast(cvar.y)); }

__global__ __launch_bounds__(NTHR, 1)
void lstm_seq_kernel(const float* __restrict__ input,
                     const float* __restrict__ W_ih1, const float* __restrict__ W_hh1,
                     const float* __restrict__ b_ih1, const float* __restrict__ b_hh1,
                     const float* __restrict__ W_ih2, const float* __restrict__ W_hh2,
                     const float* __restrict__ b_ih2, const float* __restrict__ b_hh2,
                     const float* __restrict__ W_lin, const float* __restrict__ b_lin,
                     float* __restrict__ out)
{
    extern __shared__ float sm[];
    float* sW1   = sm + OFF_W1;
    float* sW2i  = sm + OFF_W2I;
    float* sW2h  = sm + OFF_W2H;
    float* sWlin = sm + OFF_WLIN;
    float* sX    = sm + OFF_X;
    float* sH1   = sm + OFF_H1;   // [2][520]
    float* sH2   = sm + OFF_H2;   // [2][520]

    const int tid = threadIdx.x;
    const int b0  = blockIdx.x * 8;

    // ---------------- staging ----------------
    for (int i = tid; i < H4 * Hh; i += NTHR) {
        const int r = i / Hh, k = i % Hh;
        sW1[r * 52 + k]  = W_hh1[i];
        sW2i[r * 52 + k] = W_ih2[i];
        sW2h[r * 52 + k] = W_hh2[i];
    }
    for (int r = tid; r < H4; r += NTHR) {
        sW1[r * 52 + 51]  = 0.0f;
        sW2i[r * 52 + 51] = 0.0f;
        sW2h[r * 52 + 51] = 0.0f;
    }
    if (tid < 52) sWlin[tid] = (tid < Hh) ? W_lin[tid] : 0.0f;
    for (int i = tid; i < 8 * TT; i += NTHR) {
        const int b = i >> 10, t = i & 1023;
        sX[t * 8 + b] = input[b0 * TT + i];
    }
    for (int i = tid; i < 1040; i += NTHR) { sH1[i] = 0.0f; sH2[i] = 0.0f; }

    // ---------------- roles ----------------
    const int wid = tid >> 5;
    const bool isA = (wid < 7);            // L1 cell threads
    const bool isB = (wid >= 7 && wid < 20);
    const float blin = b_lin[0];

    // ----- A config: j = tid>>2 (0..55), bp = tid&3 -----
    const int jA  = tid >> 2;
    const int boA = (tid & 3) * 2;
    const bool actA = isA && (jA < Hh);
    u64 bA_i = 0, bA_f = 0, bA_g = 0, bA_o = 0;
    u64 wxi = 0, wxf = 0, wxg = 0, wxo = 0;
    const float* wA0 = sW1; const float* wA1 = sW1;
    const float* wA2 = sW1; const float* wA3 = sW1;
    if (actA) {
        const int ri = jA, rf = Hh + jA, rg = 2 * Hh + jA, ro = 3 * Hh + jA;
        bA_i = splat2(b_ih1[ri] + b_hh1[ri]);
        bA_f = splat2(b_ih1[rf] + b_hh1[rf]);
        bA_g = splat2(b_ih1[rg] + b_hh1[rg]);
        bA_o = splat2(b_ih1[ro] + b_hh1[ro]);
        wxi = splat2(W_ih1[ri]); wxf = splat2(W_ih1[rf]);
        wxg = splat2(W_ih1[rg]); wxo = splat2(W_ih1[ro]);
        wA0 = sW1 + ri * 52; wA1 = sW1 + rf * 52;
        wA2 = sW1 + rg * 52; wA3 = sW1 + ro * 52;
    }

    // ----- B config: bt = tid-224: bp = bt&3, ch = bit2, j = bt>>3 (clamped) -----
    const int bt  = tid - 224;
    const int boB = (bt & 3) * 2;
    const int chB = (bt >> 2) & 1;
    const int jBr = bt >> 3;
    const bool actB = isB && (jBr < Hh);   // store-enable
    const int jB = (jBr < Hh) ? jBr : (Hh - 1);   // clamp so all lanes run (shuffle convergence)
    u64 sB_i = 0, sB_f = 0, sB_g = 0, sB_o = 0;   // acc seeds: ch0 carries bias
    const float* wB0 = sW2i; const float* wB1 = sW2i;
    const float* wB2 = sW2i; const float* wB3 = sW2i;
    if (isB) {
        const int ri = jB, rf = Hh + jB, rg = 2 * Hh + jB, ro = 3 * Hh + jB;
        if (chB == 0) {
            sB_i = splat2(b_ih2[ri] + b_hh2[ri]);
            sB_f = splat2(b_ih2[rf] + b_hh2[rf]);
            sB_g = splat2(b_ih2[rg] + b_hh2[rg]);
            sB_o = splat2(b_ih2[ro] + b_hh2[ro]);
            wB0 = sW2i + ri * 52; wB1 = sW2i + rf * 52;
            wB2 = sW2i + rg * 52; wB3 = sW2i + ro * 52;
        } else {
            wB0 = sW2h + ri * 52; wB1 = sW2h + rf * 52;
            wB2 = sW2h + rg * 52; wB3 = sW2h + ro * 52;
        }
    }

    // ----- head config (warp 20): b = w&7, kq = w>>3 -----
    const int hw = tid - 640;
    const int hb = hw & 7;
    const int kq = hw >> 3;

    float2 c1 = make_float2(0.0f, 0.0f);
    float2 c2 = make_float2(0.0f, 0.0f);

    __syncthreads();

    // ---------------- prologue: A computes h1(0) into buf 0 ----------------
    if (actA) {
        u64 ai = bA_i, af = bA_f, ag = bA_g, ao = bA_o;
        const u64 xv = *(const u64*)(sX + 0 * 8 + boA);
        ffma2(ai, wxi, xv); ffma2(af, wxf, xv);
        ffma2(ag, wxg, xv); ffma2(ao, wxo, xv);
        const float* hrd = sH1 + 520 + boA;   // buf 1: zeros
        QUADS13(wA0, wA1, wA2, wA3, hrd);
        u64 hnew;
        UPDATE(c1, hnew);
        *(u64*)(sH1 + jA * 10 + boA) = hnew;  // h1(0) -> buf 0
    }
    __syncthreads();

    // ---------------- time loop: ONE barrier per step ----------------
    for (int t = 0; t < TT; ++t) {
        const int pt = t & 1, pn = pt ^ 1;

        if (isA) {
            if (actA) {
                // L1 cell for step t+1: reads h1(t)[pt], x(t+1); writes h1(t+1)[pn]
                u64 ai = bA_i, af = bA_f, ag = bA_g, ao = bA_o;
                const int xt = (t + 1 < TT) ? (t + 1) : t;   // last-iter result unused
                const u64 xv = *(const u64*)(sX + xt * 8 + boA);
                ffma2(ai, wxi, xv); ffma2(af, wxf, xv);
                ffma2(ag, wxg, xv); ffma2(ao, wxo, xv);
                const float* hrd = sH1 + pt * 520 + boA;
                QUADS13(wA0, wA1, wA2, wA3, hrd);
                u64 hnew;
                UPDATE(c1, hnew);
                *(u64*)(sH1 + pn * 520 + jA * 10 + boA) = hnew;
            }
        } else if (isB) {
            // L2 cell for step t, split across lane^4 pairs:
            // ch0: ih2 half (reads h1(t)[pt]); ch1: hh2 half (reads h2(t-1)[pn])
            u64 ai = sB_i, af = sB_f, ag = sB_g, ao = sB_o;
            const float* hrd = (chB ? (sH2 + pn * 520) : (sH1 + pt * 520)) + boB;
            QUADS13(wB0, wB1, wB2, wB3, hrd);
            ai = add2(ai, __shfl_xor_sync(0xffffffffu, ai, 4));
            af = add2(af, __shfl_xor_sync(0xffffffffu, af, 4));
            ag = add2(ag, __shfl_xor_sync(0xffffffffu, ag, 4));
            ao = add2(ao, __shfl_xor_sync(0xffffffffu, ao, 4));
            u64 hnew;
            UPDATE(c2, hnew);
            if (actB && chB == 0)
                *(u64*)(sH2 + pt * 520 + jB * 10 + boB) = hnew;   // h2(t)
        } else {
            // head(t-1): y = W_lin . h2(t-1)[pn] + b
            if (t >= 1) {
                const float* h2r = sH2 + pn * 520;
                float p = 0.0f;
                #pragma unroll
                for (int s = 0; s < 13; ++s) {
                    const int k = kq * 13 + s;
                    p = fmaf(sWlin[k], h2r[k * 10 + hb], p);
                }
                p += __shfl_xor_sync(0xffffffffu, p, 8);
                p += __shfl_xor_sync(0xffffffffu, p, 16);
                if (kq == 0)
                    out[(b0 + hb) * TT + (t - 1)] = p + blin;
            }
        }
        __syncthreads();
    }

    // ---------------- epilogue: head(TT-1), h2(TT-1) in buf 1 ----------------
    if (wid == 20) {
        const float* h2r = sH2 + 520;
        float p = 0.0f;
        #pragma unroll
        for (int s = 0; s < 13; ++s) {
            const int k = kq * 13 + s;
            p = fmaf(sWlin[k], h2r[k * 10 + hb], p);
        }
        p += __shfl_xor_sync(0xffffffffu, p, 8);
        p += __shfl_xor_sync(0xffffffffu, p, 16);
        if (kq == 0)
            out[(b0 + hb) * TT + (TT - 1)] = p + blin;
    }
}

extern "C" void kernel_launch(void* const* d_in, const int* in_sizes, int n_in,
                              void* d_out, int out_size) {
    const float* input = (const float*)d_in[0];
    const float* W_ih1 = (const float*)d_in[1];
    const float* W_hh1 = (const float*)d_in[2];
    const float* b_ih1 = (const float*)d_in[3];
    const float* b_hh1 = (const float*)d_in[4];
    const float* W_ih2 = (const float*)d_in[5];
    const float* W_hh2 = (const float*)d_in[6];
    const float* b_ih2 = (const float*)d_in[7];
    const float* b_hh2 = (const float*)d_in[8];
    const float* W_lin = (const float*)d_in[9];
    const float* b_lin = (const float*)d_in[10];
    float* out = (float*)d_out;

    cudaFuncSetAttribute(lstm_seq_kernel,
                         cudaFuncAttributeMaxDynamicSharedMemorySize, SMEM_BYTES);
    lstm_seq_kernel<<<NCTA, NTHR, SMEM_BYTES>>>(
        input, W_ih1, W_hh1, b_ih1, b_hh1,
        W_ih2, W_hh2, b_ih2, b_hh2, W_lin, b_lin, out);
}

// round 8
// speedup vs baseline: 1.0892x; 1.0023x over previous
#include <cuda_runtime.h>

#define Hh 51
#define H4 204
#define TT 1024
#define NCTA 128
#define NTHR 672     // warps 0-6: L1 cells; 7-19: L2 half-cells; 20: head

// ---- shared memory (float offsets) ----
// sW1 [204][52] W_hh1; sW2i [204][52] W_ih2; sW2h [204][52] W_hh2 (col 51 = 0)
// sWlin[52]; sX [1024][8] t-major; sH1 [2][52][10]; sH2 [2][52][10]
#define OFF_W1   0
#define OFF_W2I  10608
#define OFF_W2H  21216
#define OFF_WLIN 31824
#define OFF_X    31880
#define OFF_H1   40072   // mod 32 = 8
#define OFF_H2   41112   // mod 32 = 24 -> diff 16: B's h1/h2 dual loads conflict-free
#define SMEM_FLOATS 42152
#define SMEM_BYTES  (SMEM_FLOATS * 4)

typedef unsigned long long u64;

__device__ __forceinline__ u64 splat2(float w) {
    unsigned int wi = __float_as_uint(w);
    u64 r;
    asm("mov.b64 %0, {%1, %1};" : "=l"(r) : "r"(wi));
    return r;
}
__device__ __forceinline__ void ffma2(u64& d, u64 a, u64 b) {
    asm("fma.rn.f32x2 %0, %1, %2, %0;" : "+l"(d) : "l"(a), "l"(b));
}
__device__ __forceinline__ u64 add2(u64 a, u64 b) {
    u64 r;
    asm("add.rn.f32x2 %0, %1, %2;" : "=l"(r) : "l"(a), "l"(b));
    return r;
}
__device__ __forceinline__ float2 u2f(u64 v) {
    float2 f;
    asm("mov.b64 {%0, %1}, %2;" : "=f"(f.x), "=f"(f.y) : "l"(v));
    return f;
}
__device__ __forceinline__ u64 f2u(float x, float y) {
    u64 v;
    asm("mov.b64 %0, {%1, %2};" : "=l"(v) : "f"(x), "f"(y));
    return v;
}
__device__ __forceinline__ float sigf(float x) {
    return __fdividef(1.0f, 1.0f + __expf(-x));
}
__device__ __forceinline__ float tanhfast(float x) {
    return 1.0f - __fdividef(2.0f, __expf(2.0f * x) + 1.0f);
}

// 13 quads (52 k) of 4 gate rows; h rows at stride 10
#define QUADS13(wp0, wp1, wp2, wp3, hrd) { \
    _Pragma("unroll") \
    for (int kk = 0; kk < 13; ++kk) { \
        const float4 wi = *(const float4*)((wp0) + kk * 4); \
        const float4 wf = *(const float4*)((wp1) + kk * 4); \
        const float4 wg = *(const float4*)((wp2) + kk * 4); \
        const float4 wo = *(const float4*)((wp3) + kk * 4); \
        const u64 h0  = *(const u64*)((hrd) + (kk * 4 + 0) * 10); \
        const u64 h1v = *(const u64*)((hrd) + (kk * 4 + 1) * 10); \
        const u64 h2v = *(const u64*)((hrd) + (kk * 4 + 2) * 10); \
        const u64 h3v = *(const u64*)((hrd) + (kk * 4 + 3) * 10); \
        ffma2(ai, splat2(wi.x), h0);  ffma2(ai, splat2(wi.y), h1v); \
        ffma2(ai, splat2(wi.z), h2v); ffma2(ai, splat2(wi.w), h3v); \
        ffma2(af, splat2(wf.x), h0);  ffma2(af, splat2(wf.y), h1v); \
        ffma2(af, splat2(wf.z), h2v); ffma2(af, splat2(wf.w), h3v); \
        ffma2(ag, splat2(wg.x), h0);  ffma2(ag, splat2(wg.y), h1v); \
        ffma2(ag, splat2(wg.z), h2v); ffma2(ag, splat2(wg.w), h3v); \
        ffma2(ao, splat2(wo.x), h0);  ffma2(ao, splat2(wo.y), h1v); \
        ffma2(ao, splat2(wo.z), h2v); ffma2(ao, splat2(wo.w), h3v); \
    } }

#define UPDATE(cvar, hout) { \
    const float2 gi = u2f(ai), gf = u2f(af), gg = u2f(ag), go = u2f(ao); \
    const float i0 = sigf(gi.x), f0 = sigf(gf.x), g0 = tanhfast(gg.x), o0 = sigf(go.x); \
    const float i1 = sigf(gi.y), f1 = sigf(gf.y), g1 = tanhfast(gg.y), o1 = sigf(go.y); \
    cvar.x = f0 * cvar.x + i0 * g0; \
    cvar.y = f1 * cvar.y + i1 * g1; \
    hout = f2u(o0 * tanhfast(cvar.x), o1 * tanhfast(cvar.y)); }

__global__ __launch_bounds__(NTHR, 1)
void lstm_seq_kernel(const float* __restrict__ input,
                     const float* __restrict__ W_ih1, const float* __restrict__ W_hh1,
                     const float* __restrict__ b_ih1, const float* __restrict__ b_hh1,
                     const float* __restrict__ W_ih2, const float* __restrict__ W_hh2,
                     const float* __restrict__ b_ih2, const float* __restrict__ b_hh2,
                     const float* __restrict__ W_lin, const float* __restrict__ b_lin,
                     float* __restrict__ out)
{
    extern __shared__ float sm[];
    float* sW1   = sm + OFF_W1;
    float* sW2i  = sm + OFF_W2I;
    float* sW2h  = sm + OFF_W2H;
    float* sWlin = sm + OFF_WLIN;
    float* sX    = sm + OFF_X;
    float* sH1   = sm + OFF_H1;   // [2][520]
    float* sH2   = sm + OFF_H2;   // [2][520]

    const int tid = threadIdx.x;
    const int b0  = blockIdx.x * 8;

    // ---------------- staging ----------------
    for (int i = tid; i < H4 * Hh; i += NTHR) {
        const int r = i / Hh, k = i % Hh;
        sW1[r * 52 + k]  = W_hh1[i];
        sW2i[r * 52 + k] = W_ih2[i];
        sW2h[r * 52 + k] = W_hh2[i];
    }
    for (int r = tid; r < H4; r += NTHR) {
        sW1[r * 52 + 51]  = 0.0f;
        sW2i[r * 52 + 51] = 0.0f;
        sW2h[r * 52 + 51] = 0.0f;
    }
    if (tid < 52) sWlin[tid] = (tid < Hh) ? W_lin[tid] : 0.0f;
    for (int i = tid; i < 8 * TT; i += NTHR) {
        const int b = i >> 10, t = i & 1023;
        sX[t * 8 + b] = input[b0 * TT + i];
    }
    for (int i = tid; i < 1040; i += NTHR) { sH1[i] = 0.0f; sH2[i] = 0.0f; }

    // ---------------- roles ----------------
    const int wid = tid >> 5;
    const bool isA = (wid < 7);            // L1 cell threads
    const bool isB = (wid >= 7 && wid < 20);
    const float blin = b_lin[0];

    // ----- A config: j = tid>>2 (0..55), bp = tid&3 -----
    const int jA  = tid >> 2;
    const int boA = (tid & 3) * 2;
    const bool actA = isA && (jA < Hh);
    u64 bA_i = 0, bA_f = 0, bA_g = 0, bA_o = 0;
    u64 wxi = 0, wxf = 0, wxg = 0, wxo = 0;
    const float* wA0 = sW1; const float* wA1 = sW1;
    const float* wA2 = sW1; const float* wA3 = sW1;
    if (actA) {
        const int ri = jA, rf = Hh + jA, rg = 2 * Hh + jA, ro = 3 * Hh + jA;
        bA_i = splat2(b_ih1[ri] + b_hh1[ri]);
        bA_f = splat2(b_ih1[rf] + b_hh1[rf]);
        bA_g = splat2(b_ih1[rg] + b_hh1[rg]);
        bA_o = splat2(b_ih1[ro] + b_hh1[ro]);
        wxi = splat2(W_ih1[ri]); wxf = splat2(W_ih1[rf]);
        wxg = splat2(W_ih1[rg]); wxo = splat2(W_ih1[ro]);
        wA0 = sW1 + ri * 52; wA1 = sW1 + rf * 52;
        wA2 = sW1 + rg * 52; wA3 = sW1 + ro * 52;
    }

    // ----- B config: bt = tid-224: bp = bt&3, ch = bit2, j = bt>>3 (clamped) -----
    const int bt  = tid - 224;
    const int boB = (bt & 3) * 2;
    const int chB = (bt >> 2) & 1;
    const int jBr = bt >> 3;
    const bool actB = isB && (jBr < Hh);   // store-enable
    const int jB = (jBr < Hh) ? jBr : (Hh - 1);   // clamp so all lanes run (shuffle convergence)
    u64 sB_i = 0, sB_f = 0, sB_g = 0, sB_o = 0;   // acc seeds: ch0 carries bias
    const float* wB0 = sW2i; const float* wB1 = sW2i;
    const float* wB2 = sW2i; const float* wB3 = sW2i;
    if (isB) {
        const int ri = jB, rf = Hh + jB, rg = 2 * Hh + jB, ro = 3 * Hh + jB;
        if (chB == 0) {
            sB_i = splat2(b_ih2[ri] + b_hh2[ri]);
            sB_f = splat2(b_ih2[rf] + b_hh2[rf]);
            sB_g = splat2(b_ih2[rg] + b_hh2[rg]);
            sB_o = splat2(b_ih2[ro] + b_hh2[ro]);
            wB0 = sW2i + ri * 52; wB1 = sW2i + rf * 52;
            wB2 = sW2i + rg * 52; wB3 = sW2i + ro * 52;
        } else {
            wB0 = sW2h + ri * 52; wB1 = sW2h + rf * 52;
            wB2 = sW2h + rg * 52; wB3 = sW2h + ro * 52;
        }
    }

    // ----- head config (warp 20): b = w&7, kq = w>>3 -----
    const int hw = tid - 640;
    const int hb = hw & 7;
    const int kq = hw >> 3;

    float2 c1 = make_float2(0.0f, 0.0f);
    float2 c2 = make_float2(0.0f, 0.0f);

    __syncthreads();

    // ---------------- prologue: A computes h1(0) into buf 0 ----------------
    if (actA) {
        u64 ai = bA_i, af = bA_f, ag = bA_g, ao = bA_o;
        const u64 xv = *(const u64*)(sX + 0 * 8 + boA);
        ffma2(ai, wxi, xv); ffma2(af, wxf, xv);
        ffma2(ag, wxg, xv); ffma2(ao, wxo, xv);
        const float* hrd = sH1 + 520 + boA;   // buf 1: zeros
        QUADS13(wA0, wA1, wA2, wA3, hrd);
        u64 hnew;
        UPDATE(c1, hnew);
        *(u64*)(sH1 + jA * 10 + boA) = hnew;  // h1(0) -> buf 0
    }
    __syncthreads();

    // ---------------- time loop: ONE barrier per step ----------------
    for (int t = 0; t < TT; ++t) {
        const int pt = t & 1, pn = pt ^ 1;

        if (isA) {
            if (actA) {
                // L1 cell for step t+1: reads h1(t)[pt], x(t+1); writes h1(t+1)[pn]
                u64 ai = bA_i, af = bA_f, ag = bA_g, ao = bA_o;
                const int xt = (t + 1 < TT) ? (t + 1) : t;   // last-iter result unused
                const u64 xv = *(const u64*)(sX + xt * 8 + boA);
                ffma2(ai, wxi, xv); ffma2(af, wxf, xv);
                ffma2(ag, wxg, xv); ffma2(ao, wxo, xv);
                const float* hrd = sH1 + pt * 520 + boA;
                QUADS13(wA0, wA1, wA2, wA3, hrd);
                u64 hnew;
                UPDATE(c1, hnew);
                *(u64*)(sH1 + pn * 520 + jA * 10 + boA) = hnew;
            }
        } else if (isB) {
            // L2 cell for step t, split across lane^4 pairs:
            // ch0: ih2 half (reads h1(t)[pt]); ch1: hh2 half (reads h2(t-1)[pn])
            u64 ai = sB_i, af = sB_f, ag = sB_g, ao = sB_o;
            const float* hrd = (chB ? (sH2 + pn * 520) : (sH1 + pt * 520)) + boB;
            QUADS13(wB0, wB1, wB2, wB3, hrd);
            ai = add2(ai, __shfl_xor_sync(0xffffffffu, ai, 4));
            af = add2(af, __shfl_xor_sync(0xffffffffu, af, 4));
            ag = add2(ag, __shfl_xor_sync(0xffffffffu, ag, 4));
            ao = add2(ao, __shfl_xor_sync(0xffffffffu, ao, 4));
            u64 hnew;
            UPDATE(c2, hnew);
            if (actB && chB == 0)
                *(u64*)(sH2 + pt * 520 + jB * 10 + boB) = hnew;   // h2(t)
        } else {
            // head(t-1): y = W_lin . h2(t-1)[pn] + b
            if (t >= 1) {
                const float* h2r = sH2 + pn * 520;
                float p = 0.0f;
                #pragma unroll
                for (int s = 0; s < 13; ++s) {
                    const int k = kq * 13 + s;
                    p = fmaf(sWlin[k], h2r[k * 10 + hb], p);
                }
                p += __shfl_xor_sync(0xffffffffu, p, 8);
                p += __shfl_xor_sync(0xffffffffu, p, 16);
                if (kq == 0)
                    out[(b0 + hb) * TT + (t - 1)] = p + blin;
            }
        }
        __syncthreads();
    }

    // ---------------- epilogue: head(TT-1), h2(TT-1) in buf 1 ----------------
    if (wid == 20) {
        const float* h2r = sH2 + 520;
        float p = 0.0f;
        #pragma unroll
        for (int s = 0; s < 13; ++s) {
            const int k = kq * 13 + s;
            p = fmaf(sWlin[k], h2r[k * 10 + hb], p);
        }
        p += __shfl_xor_sync(0xffffffffu, p, 8);
        p += __shfl_xor_sync(0xffffffffu, p, 16);
        if (kq == 0)
            out[(b0 + hb) * TT + (TT - 1)] = p + blin;
    }
}

extern "C" void kernel_launch(void* const* d_in, const int* in_sizes, int n_in,
                              void* d_out, int out_size) {
    const float* input = (const float*)d_in[0];
    const float* W_ih1 = (const float*)d_in[1];
    const float* W_hh1 = (const float*)d_in[2];
    const float* b_ih1 = (const float*)d_in[3];
    const float* b_hh1 = (const float*)d_in[4];
    const float* W_ih2 = (const float*)d_in[5];
    const float* W_hh2 = (const float*)d_in[6];
    const float* b_ih2 = (const float*)d_in[7];
    const float* b_hh2 = (const float*)d_in[8];
    const float* W_lin = (const float*)d_in[9];
    const float* b_lin = (const float*)d_in[10];
    float* out = (float*)d_out;

    cudaFuncSetAttribute(lstm_seq_kernel,
                         cudaFuncAttributeMaxDynamicSharedMemorySize, SMEM_BYTES);
    lstm_seq_kernel<<<NCTA, NTHR, SMEM_BYTES>>>(
        input, W_ih1, W_hh1, b_ih1, b_hh1,
        W_ih2, W_hh2, b_ih2, b_hh2, W_lin, b_lin, out);
}